// round 13
// baseline (speedup 1.0000x reference)
#include <cuda_runtime.h>
#include <cuda_fp16.h>
#include <math.h>
#include <stdint.h>

#define NTOK   1024
#define HID    768
#define FFN    3072
#define NEXP   8
#define SLOTS  (NTOK * 2)
#define TILE_M 128
#define TILE_N 128
#define TILE_K 64
#define MAXROWS 3072
#define MAX_MT (MAXROWS / TILE_M)   // 24
#define NT1    (FFN / TILE_N)       // 24
#define NT2    (HID / TILE_N)       // 6
#define KSPLIT 2
#define W_ELEMS (NEXP * HID * FFN)
#define W_N8    (W_ELEMS / 8)

// per-stage: A 16K | B 16K ; three stages = 96 KB -> 2 CTAs/SM
#define OFF_A   0
#define OFF_B   16384
#define BUF_STRIDE 32768
#define STAGES 3
#define SMEM_BYTES (STAGES * BUF_STRIDE)

// ---------------- scratch ----------------------------------------------------
__device__ int   g_off[NEXP + 1];
__device__ int   g_tile_expert[MAX_MT];
__device__ int   g_slot_e[SLOTS];
__device__ int   g_slot_pos[SLOTS];
__device__ int   g_slot_row[SLOTS];
__device__ float g_slot_gate[SLOTS];
__device__ int   g_row_token[MAXROWS];
__device__ __align__(16) __half g_Xf[(size_t)MAXROWS * HID];
__device__ __align__(16) __half g_Hf[(size_t)MAXROWS * FFN];
__device__ __align__(16) __half g_W1f[(size_t)W_ELEMS];
__device__ __align__(16) __half g_W2f[(size_t)W_ELEMS];
__device__ __align__(16) float  g_Y[(size_t)KSPLIT * MAXROWS * HID];

// ---------------- helpers ----------------------------------------------------
__device__ __forceinline__ uint32_t smem_u32(const void* p) {
    uint32_t a;
    asm("{ .reg .u64 t; cvta.to.shared.u64 t, %1; cvt.u32.u64 %0, t; }" : "=r"(a) : "l"(p));
    return a;
}
__device__ __forceinline__ void cpa16(uint32_t dst, const void* src) {
    asm volatile("cp.async.cg.shared.global [%0], [%1], 16;" :: "r"(dst), "l"(src));
}
__device__ __forceinline__ void cpa_commit() {
    asm volatile("cp.async.commit_group;" ::: "memory");
}
template <int N>
__device__ __forceinline__ void cpa_wait() {
    asm volatile("cp.async.wait_group %0;" :: "n"(N) : "memory");
}
__device__ __forceinline__ void ldsm_x4(uint32_t* r, uint32_t addr) {
    asm volatile("ldmatrix.sync.aligned.m8n8.x4.shared.b16 {%0,%1,%2,%3}, [%4];"
        : "=r"(r[0]), "=r"(r[1]), "=r"(r[2]), "=r"(r[3]) : "r"(addr));
}
__device__ __forceinline__ void ldsm_x4_t(uint32_t* r, uint32_t addr) {
    asm volatile("ldmatrix.sync.aligned.m8n8.x4.trans.shared.b16 {%0,%1,%2,%3}, [%4];"
        : "=r"(r[0]), "=r"(r[1]), "=r"(r[2]), "=r"(r[3]) : "r"(addr));
}
__device__ __forceinline__ void mma_f16(float* c, const uint32_t* a, uint32_t b0, uint32_t b1) {
    asm volatile("mma.sync.aligned.m16n8k16.row.col.f32.f16.f16.f32 "
        "{%0,%1,%2,%3}, {%4,%5,%6,%7}, {%8,%9}, {%0,%1,%2,%3};"
        : "+f"(c[0]), "+f"(c[1]), "+f"(c[2]), "+f"(c[3])
        : "r"(a[0]), "r"(a[1]), "r"(a[2]), "r"(a[3]), "r"(b0), "r"(b1));
}
__device__ __forceinline__ uint32_t pack2(float f0, float f1) {
    __half2 h = __floats2half2_rn(f0, f1);
    return *reinterpret_cast<uint32_t*>(&h);
}
__device__ __forceinline__ float gelu_ex(float v) {
    return 0.5f * v * (1.f + erff(v * 0.70710678118654752f));
}
// swizzles: A [m][k] 128B rows; B [k][n] 256B rows
__device__ __forceinline__ uint32_t swA(uint32_t m, uint32_t kbyte) {
    return (m * 128 + kbyte) ^ ((m & 7) << 4);
}
__device__ __forceinline__ uint32_t swB(uint32_t k, uint32_t nbyte) {
    return (k * 256 + nbyte) ^ ((k & 7) << 4);
}

// ---------------- router (no atomics): 6 warps per token ---------------------
__global__ void __launch_bounds__(192) router_kernel(const float* __restrict__ x,
                                                     const float* __restrict__ rw) {
    __shared__ float sacc[6][NEXP];
    int tid = threadIdx.x, wid = tid >> 5, lane = tid & 31;
    int tok = blockIdx.x;

    const float4* xp4 = (const float4*)(x + (size_t)tok * HID);
    const float4* rw4 = (const float4*)rw;        // rw row = 8 floats = 2 float4

    int i4 = wid * 32 + lane;                     // 0..191 float4 -> 768 floats
    float4 xv = xp4[i4];
    float xs[4] = {xv.x, xv.y, xv.z, xv.w};
    int row = i4 * 4;

    float acc[NEXP];
#pragma unroll
    for (int e = 0; e < NEXP; e++) acc[e] = 0.f;
#pragma unroll
    for (int r = 0; r < 4; r++) {
        float4 w0 = rw4[(row + r) * 2];
        float4 w1 = rw4[(row + r) * 2 + 1];
        acc[0] += xs[r] * w0.x; acc[1] += xs[r] * w0.y;
        acc[2] += xs[r] * w0.z; acc[3] += xs[r] * w0.w;
        acc[4] += xs[r] * w1.x; acc[5] += xs[r] * w1.y;
        acc[6] += xs[r] * w1.z; acc[7] += xs[r] * w1.w;
    }
#pragma unroll
    for (int off = 16; off; off >>= 1)
#pragma unroll
        for (int e = 0; e < NEXP; e++)
            acc[e] += __shfl_xor_sync(0xFFFFFFFFu, acc[e], off);
    if (lane == 0) {
#pragma unroll
        for (int e = 0; e < NEXP; e++) sacc[wid][e] = acc[e];
    }
    __syncthreads();

    if (tid == 0) {
        float a[NEXP];
#pragma unroll
        for (int e = 0; e < NEXP; e++)
            a[e] = sacc[0][e] + sacc[1][e] + sacc[2][e]
                 + sacc[3][e] + sacc[4][e] + sacc[5][e];
        int i1 = 0; float v1 = a[0];
#pragma unroll
        for (int e = 1; e < NEXP; e++)
            if (a[e] > v1) { v1 = a[e]; i1 = e; }
        int i2 = -1; float v2 = -INFINITY;
#pragma unroll
        for (int e = 0; e < NEXP; e++)
            if (e != i1 && a[e] > v2) { v2 = a[e]; i2 = e; }
        float g1 = 1.f / (1.f + expf(v2 - v1));
        float g2 = 1.f - g1;
        int s0 = tok * 2, s1 = s0 + 1;
        g_slot_e[s0] = i1; g_slot_gate[s0] = g1;
        g_slot_e[s1] = i2; g_slot_gate[s1] = g2;
    }
}

// ---------------- scan+scatter: ballot-scan positions, full row_token fill ---
__global__ void __launch_bounds__(256) scan_scatter_kernel() {
    __shared__ int scount[NEXP];
    __shared__ int soff[NEXP + 1];
    int t = threadIdx.x, wid = t >> 5, lane = t & 31;

    // phase 1: warp w owns expert w; deterministic slot-order positions
    if (wid < NEXP) {
        int e = wid, run = 0;
#pragma unroll 4
        for (int step = 0; step < SLOTS / 32; step++) {
            int s = step * 32 + lane;
            bool f = (g_slot_e[s] == e);
            unsigned m = __ballot_sync(0xFFFFFFFFu, f);
            if (f) g_slot_pos[s] = run + __popc(m & ((1u << lane) - 1u));
            run += __popc(m);
        }
        if (lane == 0) scount[e] = run;
    }
    __syncthreads();

    if (t == 0) {
        int off = 0;
        for (int e = 0; e < NEXP; e++) {
            soff[e] = off; g_off[e] = off;
            off += ((scount[e] + TILE_M - 1) / TILE_M) * TILE_M;
        }
        soff[NEXP] = off; g_off[NEXP] = off;
    }
    __syncthreads();

    if (t < MAX_MT) {
        int rbase = t * TILE_M;
        int ex = -1;
        for (int e = 0; e < NEXP; e++)
            if (rbase >= soff[e] && rbase < soff[e + 1]) { ex = e; break; }
        g_tile_expert[t] = ex;
    }
    for (int r = t; r < MAXROWS; r += blockDim.x) g_row_token[r] = -1;
    __syncthreads();
    for (int s = t; s < SLOTS; s += blockDim.x) {
        int e   = g_slot_e[s];
        int row = soff[e] + g_slot_pos[s];
        g_slot_row[s]    = row;
        g_row_token[row] = s >> 1;
    }
}

// gather X rows into padded layout as fp16; 4 rows per CTA
__global__ void __launch_bounds__(192) xconv_kernel(const float* __restrict__ x) {
    int t = threadIdx.x;
#pragma unroll
    for (int r = 0; r < 4; r++) {
        int row = blockIdx.x * 4 + r;
        int tok = g_row_token[row];
        float4 v = make_float4(0.f, 0.f, 0.f, 0.f);
        if (tok >= 0) v = ((const float4*)(x + (size_t)tok * HID))[t];
        ((uint2*)(g_Xf + (size_t)row * HID))[t] =
            make_uint2(pack2(v.x, v.y), pack2(v.z, v.w));
    }
}

// bulk fp32 -> fp16 weight conversion: 2 float4 reads -> 1 uint4 store
__global__ void wconv_kernel(const float4* __restrict__ src, uint4* __restrict__ dst) {
    int i = blockIdx.x * blockDim.x + threadIdx.x;
    int stride = gridDim.x * blockDim.x;
    int i8 = i;
    for (; i8 + stride < W_N8; i8 += 2 * stride) {
        float4 a0 = src[2 * i8],     a1 = src[2 * i8 + 1];
        int j = i8 + stride;
        float4 b0 = src[2 * j],      b1 = src[2 * j + 1];
        dst[i8] = make_uint4(pack2(a0.x, a0.y), pack2(a0.z, a0.w),
                             pack2(a1.x, a1.y), pack2(a1.z, a1.w));
        dst[j]  = make_uint4(pack2(b0.x, b0.y), pack2(b0.z, b0.w),
                             pack2(b1.x, b1.y), pack2(b1.z, b1.w));
    }
    for (; i8 < W_N8; i8 += stride) {
        float4 a0 = src[2 * i8], a1 = src[2 * i8 + 1];
        dst[i8] = make_uint4(pack2(a0.x, a0.y), pack2(a0.z, a0.w),
                             pack2(a1.x, a1.y), pack2(a1.z, a1.w));
    }
}

// ---------------- grouped GEMM (fp16, cp.async 3-stage, interleaved issue) ---
template <bool IS_FFN1>
__global__ void __launch_bounds__(256, 2) ffn_kernel(const __half* __restrict__ wf) {
    int mt = blockIdx.x, nt = blockIdx.y;
    int e = g_tile_expert[mt];
    if (e < 0) return;

    extern __shared__ char smem[];
    uint32_t sbase = smem_u32(smem);
    int tid = threadIdx.x, wid = tid >> 5, lane = tid & 31;
    int wm = wid >> 2, wn = wid & 3;
    int rbase = mt * TILE_M;

    const int NC  = IS_FFN1 ? (HID / TILE_K) : (FFN / TILE_K / KSPLIT);  // 12 or 24
    const int LDA = IS_FFN1 ? HID : FFN;
    const int LDB = IS_FFN1 ? FFN : HID;
    const int kbase = IS_FFN1 ? 0 : blockIdx.z * (FFN / KSPLIT);

    int am  = tid >> 1;
    int akq = (tid & 1) * 32;
    const __half* aSrc = (IS_FFN1 ? g_Xf : g_Hf) + (size_t)(rbase + am) * LDA + kbase + akq;
    int bk  = tid >> 2;
    int bn8 = (tid & 3) * 8;
    const __half* bSrc = wf + (size_t)e * HID * FFN + (size_t)nt * TILE_N
                            + (size_t)(kbase + bk) * LDB + bn8;

    uint32_t aDst[4], bDst[4];
#pragma unroll
    for (int j = 0; j < 4; j++) {
        aDst[j] = OFF_A + swA(am, (akq + j * 8) * 2);
        bDst[j] = OFF_B + swB(bk, (bn8 + j * 32) * 2);
    }

    float acc[4][4][4];
#pragma unroll
    for (int mi = 0; mi < 4; mi++)
#pragma unroll
        for (int nj = 0; nj < 4; nj++)
#pragma unroll
            for (int q = 0; q < 4; q++) acc[mi][nj][q] = 0.f;

#define ISSUE(c, s) do {                                                    \
        uint32_t base_ = sbase + (s) * BUF_STRIDE;                          \
        const __half* ap_ = aSrc + (c) * TILE_K;                            \
        const __half* bp_ = bSrc + (size_t)(c) * TILE_K * LDB;              \
        cpa16(base_ + aDst[0], ap_);                                        \
        cpa16(base_ + aDst[1], ap_ + 8);                                    \
        cpa16(base_ + aDst[2], ap_ + 16);                                   \
        cpa16(base_ + aDst[3], ap_ + 24);                                   \
        cpa16(base_ + bDst[0], bp_);                                        \
        cpa16(base_ + bDst[1], bp_ + 32);                                   \
        cpa16(base_ + bDst[2], bp_ + 64);                                   \
        cpa16(base_ + bDst[3], bp_ + 96);                                   \
        cpa_commit();                                                       \
    } while (0)

    ISSUE(0, 0);
    ISSUE(1, 1);

    uint32_t a_row = wm * 64 + (lane & 15);
    uint32_t a_kc  = (lane >> 4) * 16;
    uint32_t b_k   = (lane & 7) + ((lane >> 3) & 1) * 8;
    uint32_t b_nc  = (lane >> 4) * 16;

    int s = 0;
    for (int c = 0; c < NC; c++) {
        if (c == NC - 1) cpa_wait<0>(); else cpa_wait<1>();
        __syncthreads();
        uint32_t aA = sbase + s * BUF_STRIDE, aB = aA + OFF_B;
#pragma unroll
        for (int ks = 0; ks < 4; ks++) {
            uint32_t k0 = ks * 16;
            uint32_t ah[4][4], bh[2][4];
#pragma unroll
            for (int mi = 0; mi < 4; mi++)
                ldsm_x4(ah[mi], aA + swA(a_row + mi * 16, k0 * 2 + a_kc));
#pragma unroll
            for (int ni = 0; ni < 2; ni++)
                ldsm_x4_t(bh[ni], aB + swB(k0 + b_k, (wn * 32 + ni * 16) * 2 + b_nc));
#pragma unroll
            for (int mi = 0; mi < 4; mi++)
#pragma unroll
                for (int nj = 0; nj < 4; nj++) {
                    int ni = nj >> 1, p = (nj & 1) * 2;
                    mma_f16(acc[mi][nj], ah[mi], bh[ni][p], bh[ni][p + 1]);
                }
            if (ks == 0 && c + 2 < NC) {
                int s2 = s + 2 - (s >= 1 ? STAGES : 0);
                ISSUE(c + 2, s2);
            }
        }
        if (++s == STAGES) s = 0;
    }
#undef ISSUE

    int r0 = rbase + wm * 64 + (lane >> 2);
    int c0 = nt * TILE_N + wn * 32 + (lane & 3) * 2;
    float* yplane = g_Y + (size_t)(IS_FFN1 ? 0 : blockIdx.z) * MAXROWS * HID;
#pragma unroll
    for (int mi = 0; mi < 4; mi++) {
#pragma unroll
        for (int nj = 0; nj < 4; nj++) {
            int col = c0 + nj * 8;
#pragma unroll
            for (int h = 0; h < 2; h++) {
                int row = r0 + mi * 16 + h * 8;
                if (IS_FFN1) {
                    float v0 = gelu_ex(acc[mi][nj][2 * h]);
                    float v1 = gelu_ex(acc[mi][nj][2 * h + 1]);
                    *(uint32_t*)(g_Hf + (size_t)row * FFN + col) = pack2(v0, v1);
                } else {
                    *(float2*)(yplane + (size_t)row * HID + col) =
                        make_float2(acc[mi][nj][2 * h], acc[mi][nj][2 * h + 1]);
                }
            }
        }
    }
}

// ---------------- combine: sum K-split planes, gate, write -------------------
__global__ void combine_kernel(float* __restrict__ out) {
    int n = blockIdx.x;
    int h4 = threadIdx.x * 4;
    if (h4 >= HID) return;
    int   r0 = g_slot_row[2 * n],  r1 = g_slot_row[2 * n + 1];
    float g0 = g_slot_gate[2 * n], g1 = g_slot_gate[2 * n + 1];
    const float* y0 = g_Y;
    const float* y1 = g_Y + (size_t)MAXROWS * HID;
    float4 a0 = *(const float4*)(y0 + (size_t)r0 * HID + h4);
    float4 a1 = *(const float4*)(y1 + (size_t)r0 * HID + h4);
    float4 b0 = *(const float4*)(y0 + (size_t)r1 * HID + h4);
    float4 b1 = *(const float4*)(y1 + (size_t)r1 * HID + h4);
    float4 o;
    o.x = g0 * (a0.x + a1.x) + g1 * (b0.x + b1.x);
    o.y = g0 * (a0.y + a1.y) + g1 * (b0.y + b1.y);
    o.z = g0 * (a0.z + a1.z) + g1 * (b0.z + b1.z);
    o.w = g0 * (a0.w + a1.w) + g1 * (b0.w + b1.w);
    *(float4*)(out + (size_t)n * HID + h4) = o;
}

// ---------------- launch -----------------------------------------------------
extern "C" void kernel_launch(void* const* d_in, const int* in_sizes, int n_in,
                              void* d_out, int out_size) {
    const float* x  = (const float*)d_in[0];
    const float* rw = (const float*)d_in[1];
    const float* w1 = (const float*)d_in[2];
    const float* w2 = (const float*)d_in[3];
    float* out = (float*)d_out;

    static cudaStream_t s_side = nullptr;
    static cudaEvent_t evFork = nullptr, evW1 = nullptr, evW2 = nullptr;
    if (!s_side) {
        cudaStreamCreateWithFlags(&s_side, cudaStreamNonBlocking);
        cudaEventCreateWithFlags(&evFork, cudaEventDisableTiming);
        cudaEventCreateWithFlags(&evW1,   cudaEventDisableTiming);
        cudaEventCreateWithFlags(&evW2,   cudaEventDisableTiming);
        cudaFuncSetAttribute(ffn_kernel<true>,  cudaFuncAttributeMaxDynamicSharedMemorySize, SMEM_BYTES);
        cudaFuncSetAttribute(ffn_kernel<false>, cudaFuncAttributeMaxDynamicSharedMemorySize, SMEM_BYTES);
    }

    __half* w1f; cudaGetSymbolAddress((void**)&w1f, g_W1f);
    __half* w2f; cudaGetSymbolAddress((void**)&w2f, g_W2f);

    // fork side stream: weight conversion (moderate grid -> co-schedulable)
    cudaEventRecord(evFork, 0);
    cudaStreamWaitEvent(s_side, evFork, 0);
    wconv_kernel<<<592, 256, 0, s_side>>>((const float4*)w1, (uint4*)w1f);
    cudaEventRecord(evW1, s_side);
    wconv_kernel<<<592, 256, 0, s_side>>>((const float4*)w2, (uint4*)w2f);
    cudaEventRecord(evW2, s_side);

    // main stream: routing chain (runs in leftover slots during wconv1)
    router_kernel<<<NTOK, 192>>>(x, rw);
    scan_scatter_kernel<<<1, 256>>>();
    xconv_kernel<<<MAXROWS / 4, 192>>>(x);

    cudaStreamWaitEvent(0, evW1, 0);
    ffn_kernel<true><<<dim3(MAX_MT, NT1), 256, SMEM_BYTES>>>(w1f);
    cudaStreamWaitEvent(0, evW2, 0);
    ffn_kernel<false><<<dim3(MAX_MT, NT2, KSPLIT), 256, SMEM_BYTES>>>(w2f);
    combine_kernel<<<NTOK, HID / 4>>>(out);
}

// round 14
// speedup vs baseline: 1.1074x; 1.1074x over previous
#include <cuda_runtime.h>
#include <cuda_fp16.h>
#include <math.h>
#include <stdint.h>

#define NTOK   1024
#define HID    768
#define FFN    3072
#define NEXP   8
#define SLOTS  (NTOK * 2)
#define TILE_M 128
#define TILE_N 128
#define TILE_K 64
#define MAXROWS 3072
#define MAX_MT (MAXROWS / TILE_M)   // 24
#define NT1    (FFN / TILE_N)       // 24
#define NT2    (HID / TILE_N)       // 6
#define KSPLIT 2
#define W_ELEMS (NEXP * HID * FFN)
#define W_N8    (W_ELEMS / 8)

// per-stage: A 16K | B 16K ; three stages = 96 KB -> 2 CTAs/SM
#define OFF_A   0
#define OFF_B   16384
#define BUF_STRIDE 32768
#define STAGES 3
#define SMEM_BYTES (STAGES * BUF_STRIDE)

// ---------------- scratch ----------------------------------------------------
__device__ int   g_off[NEXP + 1];
__device__ int   g_tile_expert[MAX_MT];
__device__ int   g_slot_e[SLOTS];
__device__ int   g_slot_row[SLOTS];
__device__ float g_slot_gate[SLOTS];
__device__ int   g_row_token[MAXROWS];
__device__ __align__(16) __half g_Xf[(size_t)MAXROWS * HID];
__device__ __align__(16) __half g_Hf[(size_t)MAXROWS * FFN];
__device__ __align__(16) __half g_W1f[(size_t)W_ELEMS];
__device__ __align__(16) __half g_W2f[(size_t)W_ELEMS];
__device__ __align__(16) float  g_Y[(size_t)KSPLIT * MAXROWS * HID];

// ---------------- helpers ----------------------------------------------------
__device__ __forceinline__ uint32_t smem_u32(const void* p) {
    uint32_t a;
    asm("{ .reg .u64 t; cvta.to.shared.u64 t, %1; cvt.u32.u64 %0, t; }" : "=r"(a) : "l"(p));
    return a;
}
__device__ __forceinline__ void cpa16(uint32_t dst, const void* src) {
    asm volatile("cp.async.cg.shared.global [%0], [%1], 16;" :: "r"(dst), "l"(src));
}
__device__ __forceinline__ void cpa_commit() {
    asm volatile("cp.async.commit_group;" ::: "memory");
}
template <int N>
__device__ __forceinline__ void cpa_wait() {
    asm volatile("cp.async.wait_group %0;" :: "n"(N) : "memory");
}
__device__ __forceinline__ void ldsm_x4(uint32_t* r, uint32_t addr) {
    asm volatile("ldmatrix.sync.aligned.m8n8.x4.shared.b16 {%0,%1,%2,%3}, [%4];"
        : "=r"(r[0]), "=r"(r[1]), "=r"(r[2]), "=r"(r[3]) : "r"(addr));
}
__device__ __forceinline__ void ldsm_x4_t(uint32_t* r, uint32_t addr) {
    asm volatile("ldmatrix.sync.aligned.m8n8.x4.trans.shared.b16 {%0,%1,%2,%3}, [%4];"
        : "=r"(r[0]), "=r"(r[1]), "=r"(r[2]), "=r"(r[3]) : "r"(addr));
}
__device__ __forceinline__ void mma_f16(float* c, const uint32_t* a, uint32_t b0, uint32_t b1) {
    asm volatile("mma.sync.aligned.m16n8k16.row.col.f32.f16.f16.f32 "
        "{%0,%1,%2,%3}, {%4,%5,%6,%7}, {%8,%9}, {%0,%1,%2,%3};"
        : "+f"(c[0]), "+f"(c[1]), "+f"(c[2]), "+f"(c[3])
        : "r"(a[0]), "r"(a[1]), "r"(a[2]), "r"(a[3]), "r"(b0), "r"(b1));
}
__device__ __forceinline__ uint32_t pack2(float f0, float f1) {
    __half2 h = __floats2half2_rn(f0, f1);
    return *reinterpret_cast<uint32_t*>(&h);
}
__device__ __forceinline__ float gelu_ex(float v) {
    return 0.5f * v * (1.f + erff(v * 0.70710678118654752f));
}
// swizzles: A [m][k] 128B rows; B [k][n] 256B rows
__device__ __forceinline__ uint32_t swA(uint32_t m, uint32_t kbyte) {
    return (m * 128 + kbyte) ^ ((m & 7) << 4);
}
__device__ __forceinline__ uint32_t swB(uint32_t k, uint32_t nbyte) {
    return (k * 256 + nbyte) ^ ((k & 7) << 4);
}

// ---------------- router (no atomics): 6 warps per token ---------------------
__global__ void __launch_bounds__(192) router_kernel(const float* __restrict__ x,
                                                     const float* __restrict__ rw) {
    __shared__ float sacc[6][NEXP];
    int tid = threadIdx.x, wid = tid >> 5, lane = tid & 31;
    int tok = blockIdx.x;

    const float4* xp4 = (const float4*)(x + (size_t)tok * HID);
    const float4* rw4 = (const float4*)rw;        // rw row = 8 floats = 2 float4

    int i4 = wid * 32 + lane;                     // 0..191 float4 -> 768 floats
    float4 xv = xp4[i4];
    float xs[4] = {xv.x, xv.y, xv.z, xv.w};
    int row = i4 * 4;

    float acc[NEXP];
#pragma unroll
    for (int e = 0; e < NEXP; e++) acc[e] = 0.f;
#pragma unroll
    for (int r = 0; r < 4; r++) {
        float4 w0 = rw4[(row + r) * 2];
        float4 w1 = rw4[(row + r) * 2 + 1];
        acc[0] += xs[r] * w0.x; acc[1] += xs[r] * w0.y;
        acc[2] += xs[r] * w0.z; acc[3] += xs[r] * w0.w;
        acc[4] += xs[r] * w1.x; acc[5] += xs[r] * w1.y;
        acc[6] += xs[r] * w1.z; acc[7] += xs[r] * w1.w;
    }
#pragma unroll
    for (int off = 16; off; off >>= 1)
#pragma unroll
        for (int e = 0; e < NEXP; e++)
            acc[e] += __shfl_xor_sync(0xFFFFFFFFu, acc[e], off);
    if (lane == 0) {
#pragma unroll
        for (int e = 0; e < NEXP; e++) sacc[wid][e] = acc[e];
    }
    __syncthreads();

    if (tid == 0) {
        float a[NEXP];
#pragma unroll
        for (int e = 0; e < NEXP; e++)
            a[e] = sacc[0][e] + sacc[1][e] + sacc[2][e]
                 + sacc[3][e] + sacc[4][e] + sacc[5][e];
        int i1 = 0; float v1 = a[0];
#pragma unroll
        for (int e = 1; e < NEXP; e++)
            if (a[e] > v1) { v1 = a[e]; i1 = e; }
        int i2 = -1; float v2 = -INFINITY;
#pragma unroll
        for (int e = 0; e < NEXP; e++)
            if (e != i1 && a[e] > v2) { v2 = a[e]; i2 = e; }
        float g1 = 1.f / (1.f + expf(v2 - v1));
        float g2 = 1.f - g1;
        int s0 = tok * 2, s1 = s0 + 1;
        g_slot_e[s0] = i1; g_slot_gate[s0] = g1;
        g_slot_e[s1] = i2; g_slot_gate[s1] = g2;
    }
}

// ---------------- scan+scatter: smem-staged ballot scan -----------------------
__global__ void __launch_bounds__(256) scan_scatter_kernel() {
    __shared__ int s_e[SLOTS];        // 8 KB
    __shared__ int s_pos[SLOTS];      // 8 KB
    __shared__ int scount[NEXP];
    __shared__ int soff[NEXP + 1];
    int t = threadIdx.x, wid = t >> 5, lane = t & 31;

    // stage slot->expert map into smem (coalesced, 8 per thread)
#pragma unroll
    for (int j = 0; j < SLOTS / 256; j++)
        s_e[j * 256 + t] = g_slot_e[j * 256 + t];
    __syncthreads();

    // warp w owns expert w; deterministic slot-order positions from smem
    if (wid < NEXP) {
        int e = wid, run = 0;
#pragma unroll
        for (int step = 0; step < SLOTS / 32; step++) {
            int s = step * 32 + lane;
            bool f = (s_e[s] == e);
            unsigned m = __ballot_sync(0xFFFFFFFFu, f);
            if (f) s_pos[s] = run + __popc(m & ((1u << lane) - 1u));
            run += __popc(m);
        }
        if (lane == 0) scount[e] = run;
    }
    __syncthreads();

    if (t == 0) {
        int off = 0;
        for (int e = 0; e < NEXP; e++) {
            soff[e] = off; g_off[e] = off;
            off += ((scount[e] + TILE_M - 1) / TILE_M) * TILE_M;
        }
        soff[NEXP] = off; g_off[NEXP] = off;
    }
    __syncthreads();

    if (t < MAX_MT) {
        int rbase = t * TILE_M;
        int ex = -1;
        for (int e = 0; e < NEXP; e++)
            if (rbase >= soff[e] && rbase < soff[e + 1]) { ex = e; break; }
        g_tile_expert[t] = ex;
    }
    for (int r = t; r < MAXROWS; r += blockDim.x) g_row_token[r] = -1;
    __syncthreads();
#pragma unroll
    for (int j = 0; j < SLOTS / 256; j++) {
        int s = j * 256 + t;
        int row = soff[s_e[s]] + s_pos[s];
        g_slot_row[s]    = row;
        g_row_token[row] = s >> 1;
    }
}

// gather X rows into padded layout as fp16; 4 rows per CTA
__global__ void __launch_bounds__(192) xconv_kernel(const float* __restrict__ x) {
    int t = threadIdx.x;
#pragma unroll
    for (int r = 0; r < 4; r++) {
        int row = blockIdx.x * 4 + r;
        int tok = g_row_token[row];
        float4 v = make_float4(0.f, 0.f, 0.f, 0.f);
        if (tok >= 0) v = ((const float4*)(x + (size_t)tok * HID))[t];
        ((uint2*)(g_Xf + (size_t)row * HID))[t] =
            make_uint2(pack2(v.x, v.y), pack2(v.z, v.w));
    }
}

// bulk fp32 -> fp16 weight conversion: 2 float4 reads -> 1 uint4 store
__global__ void wconv_kernel(const float4* __restrict__ src, uint4* __restrict__ dst) {
    int i = blockIdx.x * blockDim.x + threadIdx.x;
    int stride = gridDim.x * blockDim.x;
    int i8 = i;
    for (; i8 + stride < W_N8; i8 += 2 * stride) {
        float4 a0 = src[2 * i8],     a1 = src[2 * i8 + 1];
        int j = i8 + stride;
        float4 b0 = src[2 * j],      b1 = src[2 * j + 1];
        dst[i8] = make_uint4(pack2(a0.x, a0.y), pack2(a0.z, a0.w),
                             pack2(a1.x, a1.y), pack2(a1.z, a1.w));
        dst[j]  = make_uint4(pack2(b0.x, b0.y), pack2(b0.z, b0.w),
                             pack2(b1.x, b1.y), pack2(b1.z, b1.w));
    }
    for (; i8 < W_N8; i8 += stride) {
        float4 a0 = src[2 * i8], a1 = src[2 * i8 + 1];
        dst[i8] = make_uint4(pack2(a0.x, a0.y), pack2(a0.z, a0.w),
                             pack2(a1.x, a1.y), pack2(a1.z, a1.w));
    }
}

// ---------------- grouped GEMM (fp16, cp.async 3-stage, interleaved issue) ---
template <bool IS_FFN1>
__global__ void __launch_bounds__(256, 2) ffn_kernel(const __half* __restrict__ wf) {
    int mt = blockIdx.x, nt = blockIdx.y;
    int e = g_tile_expert[mt];
    if (e < 0) return;

    extern __shared__ char smem[];
    uint32_t sbase = smem_u32(smem);
    int tid = threadIdx.x, wid = tid >> 5, lane = tid & 31;
    int wm = wid >> 2, wn = wid & 3;
    int rbase = mt * TILE_M;

    const int NC  = IS_FFN1 ? (HID / TILE_K) : (FFN / TILE_K / KSPLIT);  // 12 or 24
    const int LDA = IS_FFN1 ? HID : FFN;
    const int LDB = IS_FFN1 ? FFN : HID;
    const int kbase = IS_FFN1 ? 0 : blockIdx.z * (FFN / KSPLIT);

    int am  = tid >> 1;
    int akq = (tid & 1) * 32;
    const __half* aSrc = (IS_FFN1 ? g_Xf : g_Hf) + (size_t)(rbase + am) * LDA + kbase + akq;
    int bk  = tid >> 2;
    int bn8 = (tid & 3) * 8;
    const __half* bSrc = wf + (size_t)e * HID * FFN + (size_t)nt * TILE_N
                            + (size_t)(kbase + bk) * LDB + bn8;

    uint32_t aDst[4], bDst[4];
#pragma unroll
    for (int j = 0; j < 4; j++) {
        aDst[j] = OFF_A + swA(am, (akq + j * 8) * 2);
        bDst[j] = OFF_B + swB(bk, (bn8 + j * 32) * 2);
    }

    float acc[4][4][4];
#pragma unroll
    for (int mi = 0; mi < 4; mi++)
#pragma unroll
        for (int nj = 0; nj < 4; nj++)
#pragma unroll
            for (int q = 0; q < 4; q++) acc[mi][nj][q] = 0.f;

#define ISSUE(c, s) do {                                                    \
        uint32_t base_ = sbase + (s) * BUF_STRIDE;                          \
        const __half* ap_ = aSrc + (c) * TILE_K;                            \
        const __half* bp_ = bSrc + (size_t)(c) * TILE_K * LDB;              \
        cpa16(base_ + aDst[0], ap_);                                        \
        cpa16(base_ + aDst[1], ap_ + 8);                                    \
        cpa16(base_ + aDst[2], ap_ + 16);                                   \
        cpa16(base_ + aDst[3], ap_ + 24);                                   \
        cpa16(base_ + bDst[0], bp_);                                        \
        cpa16(base_ + bDst[1], bp_ + 32);                                   \
        cpa16(base_ + bDst[2], bp_ + 64);                                   \
        cpa16(base_ + bDst[3], bp_ + 96);                                   \
        cpa_commit();                                                       \
    } while (0)

    ISSUE(0, 0);
    ISSUE(1, 1);

    uint32_t a_row = wm * 64 + (lane & 15);
    uint32_t a_kc  = (lane >> 4) * 16;
    uint32_t b_k   = (lane & 7) + ((lane >> 3) & 1) * 8;
    uint32_t b_nc  = (lane >> 4) * 16;

    int s = 0;
    for (int c = 0; c < NC; c++) {
        if (c == NC - 1) cpa_wait<0>(); else cpa_wait<1>();
        __syncthreads();
        uint32_t aA = sbase + s * BUF_STRIDE, aB = aA + OFF_B;
#pragma unroll
        for (int ks = 0; ks < 4; ks++) {
            uint32_t k0 = ks * 16;
            uint32_t ah[4][4], bh[2][4];
#pragma unroll
            for (int mi = 0; mi < 4; mi++)
                ldsm_x4(ah[mi], aA + swA(a_row + mi * 16, k0 * 2 + a_kc));
#pragma unroll
            for (int ni = 0; ni < 2; ni++)
                ldsm_x4_t(bh[ni], aB + swB(k0 + b_k, (wn * 32 + ni * 16) * 2 + b_nc));
#pragma unroll
            for (int mi = 0; mi < 4; mi++)
#pragma unroll
                for (int nj = 0; nj < 4; nj++) {
                    int ni = nj >> 1, p = (nj & 1) * 2;
                    mma_f16(acc[mi][nj], ah[mi], bh[ni][p], bh[ni][p + 1]);
                }
            if (ks == 0 && c + 2 < NC) {
                int s2 = s + 2 - (s >= 1 ? STAGES : 0);
                ISSUE(c + 2, s2);
            }
        }
        if (++s == STAGES) s = 0;
    }
#undef ISSUE

    int r0 = rbase + wm * 64 + (lane >> 2);
    int c0 = nt * TILE_N + wn * 32 + (lane & 3) * 2;
    float* yplane = g_Y + (size_t)(IS_FFN1 ? 0 : blockIdx.z) * MAXROWS * HID;
#pragma unroll
    for (int mi = 0; mi < 4; mi++) {
#pragma unroll
        for (int nj = 0; nj < 4; nj++) {
            int col = c0 + nj * 8;
#pragma unroll
            for (int h = 0; h < 2; h++) {
                int row = r0 + mi * 16 + h * 8;
                if (IS_FFN1) {
                    float v0 = gelu_ex(acc[mi][nj][2 * h]);
                    float v1 = gelu_ex(acc[mi][nj][2 * h + 1]);
                    *(uint32_t*)(g_Hf + (size_t)row * FFN + col) = pack2(v0, v1);
                } else {
                    *(float2*)(yplane + (size_t)row * HID + col) =
                        make_float2(acc[mi][nj][2 * h], acc[mi][nj][2 * h + 1]);
                }
            }
        }
    }
}

// ---------------- combine: sum K-split planes, gate, write -------------------
__global__ void combine_kernel(float* __restrict__ out) {
    int n = blockIdx.x;
    int h4 = threadIdx.x * 4;
    if (h4 >= HID) return;
    int   r0 = g_slot_row[2 * n],  r1 = g_slot_row[2 * n + 1];
    float g0 = g_slot_gate[2 * n], g1 = g_slot_gate[2 * n + 1];
    const float* y0 = g_Y;
    const float* y1 = g_Y + (size_t)MAXROWS * HID;
    float4 a0 = *(const float4*)(y0 + (size_t)r0 * HID + h4);
    float4 a1 = *(const float4*)(y1 + (size_t)r0 * HID + h4);
    float4 b0 = *(const float4*)(y0 + (size_t)r1 * HID + h4);
    float4 b1 = *(const float4*)(y1 + (size_t)r1 * HID + h4);
    float4 o;
    o.x = g0 * (a0.x + a1.x) + g1 * (b0.x + b1.x);
    o.y = g0 * (a0.y + a1.y) + g1 * (b0.y + b1.y);
    o.z = g0 * (a0.z + a1.z) + g1 * (b0.z + b1.z);
    o.w = g0 * (a0.w + a1.w) + g1 * (b0.w + b1.w);
    *(float4*)(out + (size_t)n * HID + h4) = o;
}

// ---------------- launch -----------------------------------------------------
extern "C" void kernel_launch(void* const* d_in, const int* in_sizes, int n_in,
                              void* d_out, int out_size) {
    const float* x  = (const float*)d_in[0];
    const float* rw = (const float*)d_in[1];
    const float* w1 = (const float*)d_in[2];
    const float* w2 = (const float*)d_in[3];
    float* out = (float*)d_out;

    static cudaStream_t s_side = nullptr;
    static cudaEvent_t evFork = nullptr, evW1 = nullptr, evW2 = nullptr;
    if (!s_side) {
        cudaStreamCreateWithFlags(&s_side, cudaStreamNonBlocking);
        cudaEventCreateWithFlags(&evFork, cudaEventDisableTiming);
        cudaEventCreateWithFlags(&evW1,   cudaEventDisableTiming);
        cudaEventCreateWithFlags(&evW2,   cudaEventDisableTiming);
        cudaFuncSetAttribute(ffn_kernel<true>,  cudaFuncAttributeMaxDynamicSharedMemorySize, SMEM_BYTES);
        cudaFuncSetAttribute(ffn_kernel<false>, cudaFuncAttributeMaxDynamicSharedMemorySize, SMEM_BYTES);
    }

    __half* w1f; cudaGetSymbolAddress((void**)&w1f, g_W1f);
    __half* w2f; cudaGetSymbolAddress((void**)&w2f, g_W2f);

    // fork side stream: weight conversion (moderate grid -> co-schedulable)
    cudaEventRecord(evFork, 0);
    cudaStreamWaitEvent(s_side, evFork, 0);
    wconv_kernel<<<592, 256, 0, s_side>>>((const float4*)w1, (uint4*)w1f);
    cudaEventRecord(evW1, s_side);
    wconv_kernel<<<592, 256, 0, s_side>>>((const float4*)w2, (uint4*)w2f);
    cudaEventRecord(evW2, s_side);

    // main stream: routing chain (runs in leftover slots during wconv1)
    router_kernel<<<NTOK, 192>>>(x, rw);
    scan_scatter_kernel<<<1, 256>>>();
    xconv_kernel<<<MAXROWS / 4, 192>>>(x);

    cudaStreamWaitEvent(0, evW1, 0);
    ffn_kernel<true><<<dim3(MAX_MT, NT1), 256, SMEM_BYTES>>>(w1f);
    cudaStreamWaitEvent(0, evW2, 0);
    ffn_kernel<false><<<dim3(MAX_MT, NT2, KSPLIT), 256, SMEM_BYTES>>>(w2f);
    combine_kernel<<<NTOK, HID / 4>>>(out);
}